// round 14
// baseline (speedup 1.0000x reference)
#include <cuda_runtime.h>
#include <stdint.h>

#define NN2  361
#define MM   361
#define NT   384
#define HSLOTS 4096
#define HMASK  4095
#define MAXG  64
#define MAXST 256

__device__ __forceinline__ unsigned hash_fn(int v) {
    return (((unsigned)v) * 2654435761u) >> 20;   // top 12 bits -> [0,4096)
}

__global__ __launch_bounds__(NT, 4)
void superko_kernel(const int* __restrict__ ZposT,
                    const int* __restrict__ current_player,
                    const int* __restrict__ current_hash,
                    const int* __restrict__ hash_history,
                    const int* __restrict__ move_count,
                    const int* __restrict__ legal,
                    const int* __restrict__ sidx,
                    const int* __restrict__ sptr,
                    const int* __restrict__ gptr,
                    const int* __restrict__ cap,
                    float* __restrict__ out)
{
    __shared__ int hset[HSLOTS];
    __shared__ int gxor[MAXG];
    __shared__ int sdelta[MAXST];   // general-CSR fallback only
    __shared__ int sflag;

    const int b   = blockIdx.x;
    const int tid = threadIdx.x;

    // -------- phase 0: fire all loads --------
    const int player = __ldg(&current_player[b]);
    int mc           = __ldg(&move_count[b]);
    const int ch     = __ldg(&current_hash[b]);
    if (mc > MM) mc = MM;
    if (mc < 0)  mc = 0;

    const bool hasc = (tid < NN2);

    int4 c4 = make_int4(-1, -1, -1, -1);
    int  lgv = 0, ze = 0, zb = 0, zw = 0, hv = 0;
    if (hasc) {
        c4  = ((const int4*)(cap + (long long)b * NN2 * 4))[tid];
        lgv = legal[(long long)b * NN2 + tid];
        ze  = __ldg(&ZposT[tid]);
        zb  = __ldg(&ZposT[NN2 + tid]);
        zw  = __ldg(&ZposT[2 * NN2 + tid]);
        hv  = hash_history[(long long)b * MM + tid];
    }

    // CSR scalars
    const int gstart = gptr[b];
    int ng = gptr[b + 1] - gstart;
    if (ng < 0) ng = 0;
    if (ng > MAXG) ng = MAXG;
    const int sbase = sptr[gstart];
    int nst = sptr[gstart + ng] - sbase;
    if (nst < 0) nst = 0;
    if (nst > MAXST) nst = MAXST;

    // coalesced stone gather + removal delta (opponent color)
    int sd = 0;
    if (tid < nst) {
        int c = sidx[sbase + tid];
        sd = __ldg(&ZposT[c]) ^ ((player == 0) ? __ldg(&ZposT[2 * NN2 + c])
                                               : __ldg(&ZposT[NN2 + c]));
    }

    // warp 0: parallel uniform-CSR verify
    if (tid < 32) {
        bool ok = true;
        if (tid == 0)
            ok = (nst == ng * 16) && ((nst & 31) == 0) && (ng <= 31);
        else if (tid <= ng && ng <= 31)
            ok = (sptr[gstart + tid] == sbase + 16 * tid);
        unsigned m = __ballot_sync(0xffffffffu, ok);
        if (tid == 0) sflag = (m == 0xffffffffu) ? 1 : 0;
    }

    // hset init: 16 KB = 1024 STS.128 across 384 threads (3 rounds, last guarded)
    {
        int4* h4 = (int4*)hset;
        const int4 m1 = make_int4(-1, -1, -1, -1);
        h4[tid]      = m1;
        h4[tid + NT] = m1;
        if (tid < HSLOTS / 4 - 2 * NT) h4[tid + 2 * NT] = m1;
    }

    // speculative group XOR (16-lane butterfly); fallback overwrites if needed
    if (tid < nst) {
        int d = sd;
        d ^= __shfl_xor_sync(0xffffffffu, d, 8);
        d ^= __shfl_xor_sync(0xffffffffu, d, 4);
        d ^= __shfl_xor_sync(0xffffffffu, d, 2);
        d ^= __shfl_xor_sync(0xffffffffu, d, 1);
        if ((tid & 15) == 0) gxor[tid >> 4] = d;
    }

    __syncthreads();   // barrier 1

    // -------- phase 1: insert (load factor 0.088 -> first CAS lands ~98%) --------
    if (tid < mc) {
        unsigned h = hash_fn(hv) & HMASK;
        int prev = atomicCAS(&hset[h], -1, hv);
        while (prev != -1 && prev != hv) {
            h = (h + 1) & HMASK;
            prev = atomicCAS(&hset[h], -1, hv);
        }
    }

    if (!sflag) {      // general-CSR fallback (block-uniform)
        if (tid < nst) sdelta[tid] = sd;
        __syncthreads();
        if (tid < ng) {
            int s0 = sptr[gstart + tid] - sbase;
            int s1 = sptr[gstart + tid + 1] - sbase;
            if (s0 < 0) s0 = 0;
            if (s1 > nst) s1 = nst;
            int x = 0;
            for (int s = s0; s < s1; ++s) x ^= sdelta[s];
            gxor[tid] = x;
        }
    }

    __syncthreads();   // barrier 2

    // -------- phase 2: paired branch-light probe + output --------
    if (hasc) {
        float r = 0.0f;
        if (lgv != 0) {
            int cd = 0;
            if (c4.x >= 0) cd ^= gxor[c4.x];
            if (c4.y >= 0) cd ^= gxor[c4.y];
            if (c4.z >= 0) cd ^= gxor[c4.z];
            if (c4.w >= 0) cd ^= gxor[c4.w];
            int cand = ch ^ (ze ^ ((player == 0) ? zb : zw)) ^ cd;

            // paired probe: two independent LDS per iteration, branchless resolve.
            // cand is an XOR of 31-bit values -> never equals the -1 sentinel.
            bool found = false;
            unsigned h = hash_fn(cand) & HMASK;
            while (true) {
                int v0 = hset[h];
                int v1 = hset[(h + 1) & HMASK];
                bool hit  = (v0 == cand) | ((v0 != -1) & (v1 == cand));
                bool done = hit | (v0 == -1) | (v1 == -1);
                if (done) { found = hit; break; }
                h = (h + 2) & HMASK;
            }
            r = found ? 0.0f : 1.0f;
        }
        out[(long long)b * NN2 + tid] = r;
    }
}

extern "C" void kernel_launch(void* const* d_in, const int* in_sizes, int n_in,
                              void* d_out, int out_size) {
    const int* ZposT        = (const int*)d_in[0];
    const int* cur_player   = (const int*)d_in[1];
    const int* cur_hash     = (const int*)d_in[2];
    const int* hash_hist    = (const int*)d_in[3];
    const int* mv_count     = (const int*)d_in[4];
    const int* lg           = (const int*)d_in[5];
    const int* sidx         = (const int*)d_in[6];
    const int* sptr         = (const int*)d_in[7];
    const int* gptr         = (const int*)d_in[8];
    const int* cap          = (const int*)d_in[9];

    float* out = (float*)d_out;
    const int B = in_sizes[8] - 1;   // gptr has B+1 entries

    superko_kernel<<<B, NT>>>(ZposT, cur_player, cur_hash, hash_hist,
                              mv_count, lg, sidx, sptr, gptr, cap, out);
}

// round 15
// speedup vs baseline: 1.0923x; 1.0923x over previous
#include <cuda_runtime.h>
#include <stdint.h>

#define NN2  361
#define MM   361
#define NT   512
#define HSLOTS 2048
#define HMASK  2047
#define MAXG  64
#define MAXST 256

__device__ __forceinline__ unsigned hash_fn(int v) {
    return (((unsigned)v) * 2654435761u) >> 21;   // top 11 bits -> [0,2048)
}

__global__ __launch_bounds__(NT, 4)
void superko_kernel(const int* __restrict__ ZposT,
                    const int* __restrict__ current_player,
                    const int* __restrict__ current_hash,
                    const int* __restrict__ hash_history,
                    const int* __restrict__ move_count,
                    const int* __restrict__ legal,
                    const int* __restrict__ sidx,
                    const int* __restrict__ sptr,
                    const int* __restrict__ gptr,
                    const int* __restrict__ cap,
                    float* __restrict__ out)
{
    __shared__ int hset[HSLOTS];
    __shared__ int gxor[MAXG];
    __shared__ int sdelta[MAXST];   // general-CSR fallback only
    __shared__ int sflag;

    const int b   = blockIdx.x;
    const int tid = threadIdx.x;

    // -------- phase 0: fire all loads (one cell/hist/stone per thread) --------
    const int player = __ldg(&current_player[b]);
    int mc           = __ldg(&move_count[b]);
    const int ch     = __ldg(&current_hash[b]);
    if (mc > MM) mc = MM;
    if (mc < 0)  mc = 0;

    const bool hasc = (tid < NN2);

    int4 c4 = make_int4(-1, -1, -1, -1);
    int  lgv = 0, ze = 0, zb = 0, zw = 0, hv = 0;
    if (hasc) {
        c4  = ((const int4*)(cap + (long long)b * NN2 * 4))[tid];
        lgv = legal[(long long)b * NN2 + tid];
        ze  = __ldg(&ZposT[tid]);
        zb  = __ldg(&ZposT[NN2 + tid]);
        zw  = __ldg(&ZposT[2 * NN2 + tid]);
        hv  = hash_history[(long long)b * MM + tid];
    }

    // CSR scalars
    const int gstart = gptr[b];
    int ng = gptr[b + 1] - gstart;
    if (ng < 0) ng = 0;
    if (ng > MAXG) ng = MAXG;
    const int sbase = sptr[gstart];
    int nst = sptr[gstart + ng] - sbase;
    if (nst < 0) nst = 0;
    if (nst > MAXST) nst = MAXST;

    // coalesced stone gather + removal delta (opponent color)
    int sd = 0;
    if (tid < nst) {
        int c = sidx[sbase + tid];
        sd = __ldg(&ZposT[c]) ^ ((player == 0) ? __ldg(&ZposT[2 * NN2 + c])
                                               : __ldg(&ZposT[NN2 + c]));
    }

    // warp 0: parallel uniform-CSR verify
    if (tid < 32) {
        bool ok = true;
        if (tid == 0)
            ok = (nst == ng * 16) && ((nst & 31) == 0) && (ng <= 31);
        else if (tid <= ng && ng <= 31)
            ok = (sptr[gstart + tid] == sbase + 16 * tid);
        unsigned m = __ballot_sync(0xffffffffu, ok);
        if (tid == 0) sflag = (m == 0xffffffffu) ? 1 : 0;
    }

    // hset init: 2048 slots = exactly one STS.128 per thread
    ((int4*)hset)[tid] = make_int4(-1, -1, -1, -1);

    // speculative group XOR (16-lane butterfly); fallback overwrites if needed
    if (tid < nst) {
        int d = sd;
        d ^= __shfl_xor_sync(0xffffffffu, d, 8);
        d ^= __shfl_xor_sync(0xffffffffu, d, 4);
        d ^= __shfl_xor_sync(0xffffffffu, d, 2);
        d ^= __shfl_xor_sync(0xffffffffu, d, 1);
        if ((tid & 15) == 0) gxor[tid >> 4] = d;
    }

    __syncthreads();   // barrier 1

    // -------- phase 1: single insert round (mc <= 361 < NT) --------
    if (tid < mc) {
        unsigned h = hash_fn(hv) & HMASK;
        int prev = atomicCAS(&hset[h], -1, hv);
        while (prev != -1 && prev != hv) {
            h = (h + 1) & HMASK;
            prev = atomicCAS(&hset[h], -1, hv);
        }
    }

    if (!sflag) {      // general-CSR fallback (block-uniform)
        if (tid < nst) sdelta[tid] = sd;
        __syncthreads();
        if (tid < ng) {
            int s0 = sptr[gstart + tid] - sbase;
            int s1 = sptr[gstart + tid + 1] - sbase;
            if (s0 < 0) s0 = 0;
            if (s1 > nst) s1 = nst;
            int x = 0;
            for (int s = s0; s < s1; ++s) x ^= sdelta[s];
            gxor[tid] = x;
        }
    }

    __syncthreads();   // barrier 2

    // -------- phase 2: paired branch-light probe + output --------
    if (hasc) {
        float r = 0.0f;
        if (lgv != 0) {
            int cd = 0;
            if (c4.x >= 0) cd ^= gxor[c4.x];
            if (c4.y >= 0) cd ^= gxor[c4.y];
            if (c4.z >= 0) cd ^= gxor[c4.z];
            if (c4.w >= 0) cd ^= gxor[c4.w];
            int cand = ch ^ (ze ^ ((player == 0) ? zb : zw)) ^ cd;

            // paired probe: two independent LDS per iteration, branchless resolve.
            // cand is an XOR of 31-bit values -> never equals the -1 sentinel.
            bool found = false;
            unsigned h = hash_fn(cand) & HMASK;
            while (true) {
                int v0 = hset[h];
                int v1 = hset[(h + 1) & HMASK];
                bool hit  = (v0 == cand) | ((v0 != -1) & (v1 == cand));
                bool done = hit | (v0 == -1) | (v1 == -1);
                if (done) { found = hit; break; }
                h = (h + 2) & HMASK;
            }
            r = found ? 0.0f : 1.0f;
        }
        out[(long long)b * NN2 + tid] = r;
    }
}

extern "C" void kernel_launch(void* const* d_in, const int* in_sizes, int n_in,
                              void* d_out, int out_size) {
    const int* ZposT        = (const int*)d_in[0];
    const int* cur_player   = (const int*)d_in[1];
    const int* cur_hash     = (const int*)d_in[2];
    const int* hash_hist    = (const int*)d_in[3];
    const int* mv_count     = (const int*)d_in[4];
    const int* lg           = (const int*)d_in[5];
    const int* sidx         = (const int*)d_in[6];
    const int* sptr         = (const int*)d_in[7];
    const int* gptr         = (const int*)d_in[8];
    const int* cap          = (const int*)d_in[9];

    float* out = (float*)d_out;
    const int B = in_sizes[8] - 1;   // gptr has B+1 entries

    superko_kernel<<<B, NT>>>(ZposT, cur_player, cur_hash, hash_hist,
                              mv_count, lg, sidx, sptr, gptr, cap, out);
}